// round 2
// baseline (speedup 1.0000x reference)
#include <cuda_runtime.h>
#include <math.h>

#define BB 2
#define CC 32
#define EE 128
#define SS 64
#define VV (SS*SS*SS)       /* 262144 = 2^18 */
#define KV 343

/* ---- scratch (static __device__: allocation-free per harness rules) ---- */
__device__ float g_y[(size_t)BB*CC*VV];   /* depthwise-conv output (valid at active voxels only) */
__device__ int   g_list[BB*VV];           /* compacted active voxel ids: id = b*V + v */
__device__ int   g_cnt;

/* ---------------- K0: reset counter ---------------- */
__global__ void k0_reset() { if (threadIdx.x == 0) g_cnt = 0; }

/* ---------------- K1: xm = x*m -> out (residual base), build active list -------- */
__global__ __launch_bounds__(256) void k1_mask_pack(
    const float* __restrict__ x, const int* __restrict__ mask,
    float* __restrict__ out)
{
    int i = blockIdx.x * blockDim.x + threadIdx.x;   /* i in [0, B*V), exact grid */
    int b = i >> 18;
    int v = i & (VV - 1);
    int m = mask[i];
    float fm = (float)m;
    const float* xb = x   + (size_t)b * CC * VV + v;
    float*       ob = out + (size_t)b * CC * VV + v;
#pragma unroll
    for (int c = 0; c < CC; c++)
        ob[(size_t)c * VV] = xb[(size_t)c * VV] * fm;

    /* warp-aggregated compaction push */
    unsigned act = __ballot_sync(0xffffffffu, m != 0);
    if (act) {
        int lane   = threadIdx.x & 31;
        int leader = __ffs(act) - 1;
        int base = 0;
        if (lane == leader) base = atomicAdd(&g_cnt, __popc(act));
        base = __shfl_sync(0xffffffffu, base, leader);
        if (m) g_list[base + __popc(act & ((1u << lane) - 1u))] = i;
    }
}

/* ---------------- K2: depthwise 7x7x7 conv, smem-tiled ----------------
 * Tile: 32(x) x 4(y) x 8(z) outputs. Input tile 38x10x14 (halo 3).
 * 128 threads = 32x * 4y; each thread: 8 z-outputs via z sliding window.
 * Warp spans 32 consecutive x -> all smem window loads conflict-free;
 * weights warp-uniform (broadcast LDS).
 */
#define TX 32
#define TY 4
#define TZ 8
#define IXW 38
#define IYW 10
#define IZW 14
#define SXP 40   /* padded x stride */

__global__ __launch_bounds__(128) void k2_dwconv(
    const float* __restrict__ xm,        /* = out buffer (holds x*m) */
    const int*   __restrict__ mask,
    const float* __restrict__ w_dw,
    const float* __restrict__ b_dw)
{
    __shared__ float s_in[IZW * IYW * SXP];
    __shared__ float s_w[KV];

    int c = blockIdx.y, b = blockIdx.z;
    int t  = blockIdx.x;                 /* 256 tiles: 2x * 16y * 8z */
    int xt = t & 1;
    int yt = (t >> 1) & 15;
    int zt = t >> 5;
    int x0 = xt * TX, y0 = yt * TY, z0 = zt * TZ;
    int tid = threadIdx.x;

    const float* wsrc = w_dw + c * KV;
    for (int j = tid; j < KV; j += 128) s_w[j] = wsrc[j];

    const float* src = xm + (size_t)(b * CC + c) * VV;
    for (int j = tid; j < IZW * IYW * IXW; j += 128) {
        int lz = j / (IYW * IXW);
        int r  = j - lz * (IYW * IXW);
        int ly = r / IXW;
        int lx = r - ly * IXW;
        int gz = z0 - 3 + lz, gy = y0 - 3 + ly, gx = x0 - 3 + lx;
        float val = 0.f;
        if (((unsigned)gz < SS) & ((unsigned)gy < SS) & ((unsigned)gx < SS))
            val = src[gz * 4096 + gy * 64 + gx];
        s_in[(lz * IYW + ly) * SXP + lx] = val;
    }
    __syncthreads();

    int tx = tid & 31, ty = tid >> 5;
    float acc[TZ];
#pragma unroll
    for (int k = 0; k < TZ; k++) acc[k] = 0.f;

#pragma unroll 1                 /* keep code ~9KB: fits I$ */
    for (int dy = 0; dy < 7; dy++) {
        const float* base = s_in + (ty + dy) * SXP + tx;
#pragma unroll
        for (int dx = 0; dx < 7; dx++) {
            float win[14];
#pragma unroll
            for (int j = 0; j < 14; j++)
                win[j] = base[j * (IYW * SXP) + dx];
#pragma unroll
            for (int dz = 0; dz < 7; dz++) {
                float w = s_w[(dz * 7 + dy) * 7 + dx];
#pragma unroll
                for (int k = 0; k < TZ; k++)
                    acc[k] = fmaf(w, win[k + dz], acc[k]);
            }
        }
    }

    float bd = b_dw[c];
    int gx = x0 + tx, gy = y0 + ty;
    const int* mk  = mask + b * VV;
    float*     dst = g_y + (size_t)(b * CC + c) * VV;
#pragma unroll
    for (int k = 0; k < TZ; k++) {
        int v = (z0 + k) * 4096 + gy * 64 + gx;
        if (mk[v]) dst[v] = acc[k] + bd;     /* y only needed at active voxels */
    }
}

/* ---------------- K3: LN + expand/GELU + project + residual add ----------------
 * One thread = 2 active voxels (weight LDS amortized). Weights in smem,
 * read as broadcast float4 -> ~0.125 LDS per FMA (FMA-bound).
 */
__device__ __forceinline__ float gelu_f(float x) {
    return 0.5f * x * (1.f + erff(x * 0.70710678118654752440f));
}

__global__ __launch_bounds__(128) void k3_mlp(
    const float* __restrict__ ln_g, const float* __restrict__ ln_b,
    const float* __restrict__ w2,   const float* __restrict__ b2,
    const float* __restrict__ w3,   const float* __restrict__ b3,
    float* __restrict__ out)
{
    int n = g_cnt;
    int blk0 = blockIdx.x * 256;
    if (blk0 >= n) return;

    __shared__ __align__(16) float w2s[EE * CC];
    __shared__ __align__(16) float w3s[CC * EE];
    __shared__ float b2s[EE];
    __shared__ float prm[3 * CC];   /* ln_g | ln_b | b3 */

    int tid = threadIdx.x;
    for (int j = tid; j < EE * CC; j += 128) { w2s[j] = w2[j]; w3s[j] = w3[j]; }
    b2s[tid] = b2[tid];
    if (tid < CC) { prm[tid] = ln_g[tid]; prm[CC + tid] = ln_b[tid]; prm[2 * CC + tid] = b3[tid]; }
    __syncthreads();

    int  slot0 = blk0 + tid;
    int  slot1 = slot0 + 128;
    bool ok[2] = { slot0 < n, slot1 < n };
    int  id[2];
    id[0] = ok[0] ? g_list[slot0] : g_list[blk0];
    id[1] = ok[1] ? g_list[slot1] : g_list[blk0];

    float yv[2][CC];
#pragma unroll
    for (int p = 0; p < 2; p++) {
        int bI = id[p] >> 18, vI = id[p] & (VV - 1);
        const float* yp = g_y + (size_t)bI * CC * VV + vI;
#pragma unroll
        for (int c = 0; c < CC; c++) yv[p][c] = yp[(size_t)c * VV];
    }

    /* per-voxel LayerNorm over channels (thread-local, no reduction) */
    float o[2][CC];
#pragma unroll
    for (int p = 0; p < 2; p++) {
        float s = 0.f;
#pragma unroll
        for (int c = 0; c < CC; c++) s += yv[p][c];
        float mu = s * (1.f / CC);
        float vs = 0.f;
#pragma unroll
        for (int c = 0; c < CC; c++) { float d = yv[p][c] - mu; vs = fmaf(d, d, vs); }
        float rs = rsqrtf(vs * (1.f / CC) + 1e-6f);
#pragma unroll
        for (int c = 0; c < CC; c++)
            yv[p][c] = fmaf((yv[p][c] - mu) * rs, prm[c], prm[CC + c]);
#pragma unroll
        for (int c = 0; c < CC; c++) o[p][c] = prm[2 * CC + c];
    }

    const float4* w2v = (const float4*)w2s;
    const float4* w3v = (const float4*)w3s;

#pragma unroll 1
    for (int ec = 0; ec < EE; ec += 8) {
        float h[2][8];
#pragma unroll
        for (int j = 0; j < 8; j++) {
            float z0 = b2s[ec + j], z1 = z0;
#pragma unroll
            for (int q = 0; q < CC / 4; q++) {
                float4 w = w2v[(ec + j) * (CC / 4) + q];
                z0 = fmaf(yv[0][4*q+0], w.x, z0); z1 = fmaf(yv[1][4*q+0], w.x, z1);
                z0 = fmaf(yv[0][4*q+1], w.y, z0); z1 = fmaf(yv[1][4*q+1], w.y, z1);
                z0 = fmaf(yv[0][4*q+2], w.z, z0); z1 = fmaf(yv[1][4*q+2], w.z, z1);
                z0 = fmaf(yv[0][4*q+3], w.w, z0); z1 = fmaf(yv[1][4*q+3], w.w, z1);
            }
            h[0][j] = gelu_f(z0);
            h[1][j] = gelu_f(z1);
        }
#pragma unroll
        for (int cc2 = 0; cc2 < CC; cc2++) {
            float4 a  = w3v[cc2 * (EE / 4) + (ec >> 2)];
            float4 bq = w3v[cc2 * (EE / 4) + (ec >> 2) + 1];
#pragma unroll
            for (int p = 0; p < 2; p++) {
                float acc = o[p][cc2];
                acc = fmaf(h[p][0], a.x,  acc);
                acc = fmaf(h[p][1], a.y,  acc);
                acc = fmaf(h[p][2], a.z,  acc);
                acc = fmaf(h[p][3], a.w,  acc);
                acc = fmaf(h[p][4], bq.x, acc);
                acc = fmaf(h[p][5], bq.y, acc);
                acc = fmaf(h[p][6], bq.z, acc);
                acc = fmaf(h[p][7], bq.w, acc);
                o[p][cc2] = acc;
            }
        }
    }

#pragma unroll
    for (int p = 0; p < 2; p++) {
        if (!ok[p]) continue;
        int bI = id[p] >> 18, vI = id[p] & (VV - 1);
        float* op = out + (size_t)bI * CC * VV + vI;
#pragma unroll
        for (int c = 0; c < CC; c++)
            op[(size_t)c * VV] += o[p][c];      /* out held xm -> xm + o */
    }
}

/* ---------------- launcher ---------------- */
extern "C" void kernel_launch(void* const* d_in, const int* in_sizes, int n_in,
                              void* d_out, int out_size)
{
    const float* x    = (const float*)d_in[0];
    const int*   mask = (const int*)  d_in[1];
    const float* w_dw = (const float*)d_in[2];
    const float* b_dw = (const float*)d_in[3];
    const float* ln_g = (const float*)d_in[4];
    const float* ln_b = (const float*)d_in[5];
    const float* w2   = (const float*)d_in[6];
    const float* b2   = (const float*)d_in[7];
    const float* w3   = (const float*)d_in[8];
    const float* b3   = (const float*)d_in[9];
    float* out = (float*)d_out;

    k0_reset<<<1, 32>>>();
    k1_mask_pack<<<(BB * VV) / 256, 256>>>(x, mask, out);
    dim3 g2(256, CC, BB);
    k2_dwconv<<<g2, 128>>>(out, mask, w_dw, b_dw);
    k3_mlp<<<(BB * VV) / 256, 128>>>(ln_g, ln_b, w2, b2, w3, b3, out);
}